// round 16
// baseline (speedup 1.0000x reference)
#include <cuda_runtime.h>
#include <cuda_bf16.h>
#include <cstdint>
#include <cstddef>

#define D_    768
#define H_    12
#define DK_   64
#define DFF_  3072
#define L_    12
#define NC_   100
#define S_    512
#define B_    16
#define ROWS  (B_*S_)          // 8192
#define BH_   (B_*H_)          // 192
#define QKVN  2304
#define QKN   1536

typedef __nv_bfloat16 bf16;

// ---------------- scratch (static device globals; no allocation) ----------
__device__ __align__(256) float g_x   [ROWS*(size_t)D_];
__device__ __align__(256) float g_xt  [ROWS*(size_t)D_];
__device__ __align__(256) float g_part[2*ROWS*(size_t)D_];   // split-K partials
__device__ __align__(256) float g_qkt [ROWS*(size_t)QKN];
__device__ __align__(256) bf16  g_vh  [ROWS*(size_t)D_];
__device__ __align__(256) bf16  g_vl  [ROWS*(size_t)D_];
__device__ __align__(256) float g_ct  [ROWS*(size_t)D_];
__device__ __align__(256) float g_ft  [ROWS*(size_t)DFF_];
__device__ __align__(256) float g_wqkvt[(size_t)L_*QKVN*D_];
__device__ __align__(256) float g_wot [(size_t)L_*D_*D_];
__device__ __align__(256) float g_w1t [(size_t)L_*DFF_*D_];
__device__ __align__(256) float g_w2t [(size_t)L_*DFF_*D_];
__device__ __align__(256) float g_bqkv[(size_t)L_*QKVN];
__device__ __align__(256) float g_pool[B_*D_];
__device__ __align__(256) float g_chd [B_*(D_/2)];

// ---------------- helpers ---------------------------------------------------
__device__ __forceinline__ uint32_t smem_u32(const void* p) {
    uint32_t a;
    asm("{ .reg .u64 t; cvta.to.shared.u64 t, %1; cvt.u32.u64 %0, t; }" : "=r"(a) : "l"(p));
    return a;
}
__device__ __forceinline__ float tf32r(float v) {
    uint32_t o; asm("cvt.rna.tf32.f32 %0, %1;" : "=r"(o) : "f"(v));
    return __uint_as_float(o);
}
__device__ __forceinline__ void split_bf16(float v, bf16& h, bf16& l) {
    h = __float2bfloat16(v);
    l = __float2bfloat16(v - __bfloat162float(h));
}
__device__ __forceinline__ void split2(float a, float b, uint32_t& hp, uint32_t& lp) {
    bf16 h0, l0, h1, l1;
    split_bf16(a, h0, l0); split_bf16(b, h1, l1);
    __nv_bfloat162 hv; hv.x = h0; hv.y = h1;
    __nv_bfloat162 lv; lv.x = l0; lv.y = l1;
    hp = *(uint32_t*)&hv; lp = *(uint32_t*)&lv;
}
__device__ __forceinline__ void ldsm4(uint32_t* r, uint32_t a) {
    asm volatile("ldmatrix.sync.aligned.m8n8.x4.shared.b16 {%0,%1,%2,%3}, [%4];"
        : "=r"(r[0]), "=r"(r[1]), "=r"(r[2]), "=r"(r[3]) : "r"(a));
}
__device__ __forceinline__ void ldsm4t(uint32_t* r, uint32_t a) {
    asm volatile("ldmatrix.sync.aligned.m8n8.x4.trans.shared.b16 {%0,%1,%2,%3}, [%4];"
        : "=r"(r[0]), "=r"(r[1]), "=r"(r[2]), "=r"(r[3]) : "r"(a));
}
__device__ __forceinline__ void mma16816(float* c, const uint32_t* a, const uint32_t* b) {
    asm volatile("mma.sync.aligned.m16n8k16.row.col.f32.bf16.bf16.f32 "
        "{%0,%1,%2,%3}, {%4,%5,%6,%7}, {%8,%9}, {%0,%1,%2,%3};"
        : "+f"(c[0]), "+f"(c[1]), "+f"(c[2]), "+f"(c[3])
        : "r"(a[0]), "r"(a[1]), "r"(a[2]), "r"(a[3]), "r"(b[0]), "r"(b[1]));
}
__device__ __forceinline__ void mma_tf32(float* c, const uint32_t* a, uint32_t b0, uint32_t b1) {
    asm volatile("mma.sync.aligned.m16n8k8.row.col.f32.tf32.tf32.f32 "
        "{%0,%1,%2,%3}, {%4,%5,%6,%7}, {%8,%9}, {%0,%1,%2,%3};"
        : "+f"(c[0]), "+f"(c[1]), "+f"(c[2]), "+f"(c[3])
        : "r"(a[0]), "r"(a[1]), "r"(a[2]), "r"(a[3]), "r"(b0), "r"(b1));
}
__device__ __forceinline__ void cpasync16(uint32_t dst, const void* src) {
    asm volatile("cp.async.cg.shared.global [%0], [%1], 16;" :: "r"(dst), "l"(src));
}
__device__ __forceinline__ uint32_t swq(int r, int s) {
    return (uint32_t)(((s & 8) | ((s ^ r) & 7)) << 4);
}

// ---------------- embedding + PE -------------------------------------------
__global__ __launch_bounds__(256) void embed_kernel(
    const int* __restrict__ ids, const float* __restrict__ emb,
    float* __restrict__ x, float* __restrict__ xt)
{
    int row = blockIdx.x;
    int s   = row & (S_-1);
    int tok = ids[row];
    size_t base = (size_t)row * D_;
    const float NEG = -9.210340371976184f / (float)D_;
    #pragma unroll
    for (int i = 0; i < 3; i++) {
        int d = threadIdx.x + i*256;
        int k2 = (d >> 1) << 1;
        float ang = (float)s * __expf((float)k2 * NEG);
        float pe  = (d & 1) ? cosf(ang) : sinf(ang);
        float v = emb[(size_t)tok * D_ + d] + pe;
        x[base + d] = v;
        xt[base + d] = tf32r(v);
    }
}

// ---------------- weight prep -----------------------------------------------
__global__ __launch_bounds__(256) void wprep_qkv3(
    const float* __restrict__ Wq, const float* __restrict__ Wk,
    const float* __restrict__ Wv, float* __restrict__ Tt)
{
    __shared__ float t[32][33];
    int tx = threadIdx.x & 31, ty = threadIdx.x >> 5;
    int n0 = blockIdx.x * 32, k0 = blockIdx.y * 32;
    int z = blockIdx.z, l = z / 3, m = z % 3;
    const float* W = (m == 0 ? Wq : m == 1 ? Wk : Wv) + (size_t)l * D_ * D_;
    size_t obase = (size_t)z * D_ * D_;
    #pragma unroll
    for (int i = ty; i < 32; i += 8)
        t[i][tx] = W[(size_t)(k0 + i) * D_ + n0 + tx];
    __syncthreads();
    #pragma unroll
    for (int i = ty; i < 32; i += 8)
        Tt[obase + (size_t)(n0 + i) * D_ + k0 + tx] = tf32r(t[tx][i]);
}

__global__ __launch_bounds__(256) void wprep_rest(
    const float* __restrict__ wo, const float* __restrict__ w1,
    const float* __restrict__ w2,
    const float* __restrict__ bq, const float* __restrict__ bk,
    const float* __restrict__ bv,
    float* __restrict__ wot, float* __restrict__ w1t, float* __restrict__ w2t,
    float* __restrict__ bqkv)
{
    int bx = blockIdx.x, l = blockIdx.y;
    if (bx >= 5184) {
        for (int j = threadIdx.x; j < QKVN; j += 256) {
            float v = (j < 768) ? bq[l*768 + j]
                    : (j < 1536) ? bk[l*768 + j - 768]
                                 : bv[l*768 + j - 1536];
            bqkv[(size_t)l*QKVN + j] = v;
        }
        return;
    }
    __shared__ float t[32][33];
    int tx = threadIdx.x & 31, ty = threadIdx.x >> 5;
    const float* W; float* Tt; int K, N, n0, k0;
    if (bx < 576) {
        K = D_; N = D_;  n0 = (bx % 24)*32; k0 = (bx / 24)*32;
        W = wo + (size_t)l*D_*D_;  Tt = wot + (size_t)l*D_*D_;
    } else if (bx < 2880) {
        int i = bx - 576;
        K = D_; N = DFF_; n0 = (i % 96)*32; k0 = (i / 96)*32;
        W = w1 + (size_t)l*D_*DFF_; Tt = w1t + (size_t)l*D_*DFF_;
    } else {
        int i = bx - 2880;
        K = DFF_; N = D_; n0 = (i % 24)*32; k0 = (i / 24)*32;
        W = w2 + (size_t)l*DFF_*D_; Tt = w2t + (size_t)l*DFF_*D_;
    }
    #pragma unroll
    for (int i = ty; i < 32; i += 8)
        t[i][tx] = W[(size_t)(k0 + i) * N + n0 + tx];
    __syncthreads();
    #pragma unroll
    for (int i = ty; i < 32; i += 8)
        Tt[(size_t)(n0 + i) * K + k0 + tx] = tf32r(t[tx][i]);
}

// ---------------- tf32 warp-MMA GEMM (8 warps x 32x64) ----------------------
// NCH = K-chunks per CTA (k offset = blockIdx.z * NCH*32 for split-K).
// MODE: 2 bias+relu+tf32->Ct | 3 qkv split | 4 split-K partial -> Cf (no bias)
#define TILEF 16384           // 128 rows * 128B
#define BUFF  32768           // A + B per stage
#define GSMEM (3*BUFF)        // 98304; x2 CTAs = 192KB

template<int NCH, int MODE>
__global__ __launch_bounds__(256, 2) void gemm_tf32(
    const float* __restrict__ A, int lda,
    const float* __restrict__ Bt, int ldb,
    const float* __restrict__ bias,
    float* __restrict__ Cf, bf16* __restrict__ Ch, bf16* __restrict__ Cl,
    float* __restrict__ Ct, int ldo)
{
    extern __shared__ char smx[];
    uint32_t sb = smem_u32(smx);
    int tid = threadIdx.x, lane = tid & 31, wid = tid >> 5;
    int bx = blockIdx.x, by = blockIdx.y, bz = blockIdx.z;
    int wm = wid & 3, wn = wid >> 2;

    float acc[2][8][4];
    #pragma unroll
    for (int i = 0; i < 2; i++)
        #pragma unroll
        for (int j = 0; j < 8; j++)
            #pragma unroll
            for (int q = 0; q < 4; q++) acc[i][j][q] = 0.f;

    int r0 = tid >> 3, s0 = tid & 7;
    int kofs = bz * (NCH*32);
    const float* srcA = A  + (size_t)(by*128 + r0)*lda + kofs + s0*4;
    const float* srcB = Bt + (size_t)(bx*128 + r0)*ldb + kofs + s0*4;
    uint32_t dstoff = (uint32_t)(r0*128 + ((s0 ^ (r0 & 7)) << 4));
    size_t stepA = (size_t)32*lda, stepB = (size_t)32*ldb;

    int arow = wm*32 + (lane & 15);
    int brow = wn*64 + (lane & 15);
    uint32_t half = (uint32_t)(lane >> 4);
    uint32_t aR = (uint32_t)arow*128, bR = (uint32_t)brow*128;
    uint32_t ax = (uint32_t)(arow & 7), bxr = (uint32_t)(brow & 7);

    auto loadc = [&](uint32_t dbase) {
        #pragma unroll
        for (int j = 0; j < 4; j++)
            cpasync16(dbase + dstoff + j*4096, srcA + j*stepA);
        #pragma unroll
        for (int j = 0; j < 4; j++)
            cpasync16(dbase + TILEF + dstoff + j*4096, srcB + j*stepB);
        asm volatile("cp.async.commit_group;" ::: "memory");
        srcA += 32; srcB += 32;
    };

    loadc(sb);
    loadc(sb + BUFF);

#define GBODY(KT, ST)                                                          \
    {                                                                          \
        if ((KT) + 1 < NCH) asm volatile("cp.async.wait_group 1;" ::: "memory"); \
        else                asm volatile("cp.async.wait_group 0;" ::: "memory"); \
        __syncthreads();                                                       \
        if ((KT) + 2 < NCH) loadc(sb + (((ST) + 2) % 3)*BUFF);                 \
        uint32_t abase = sb + (ST)*BUFF;                                       \
        uint32_t bbase = abase + TILEF;                                        \
        _Pragma("unroll")                                                      \
        for (int ks = 0; ks < 4; ks++) {                                       \
            uint32_t slot = 2*ks + half;                                       \
            uint32_t aF[2][4], bF[4][4];                                       \
            _Pragma("unroll")                                                  \
            for (int mt = 0; mt < 2; mt++)                                     \
                ldsm4(aF[mt], abase + aR + mt*2048 + ((slot ^ ax) << 4));      \
            _Pragma("unroll")                                                  \
            for (int np = 0; np < 4; np++)                                     \
                ldsm4(bF[np], bbase + bR + np*2048 + ((slot ^ bxr) << 4));     \
            _Pragma("unroll")                                                  \
            for (int mt = 0; mt < 2; mt++)                                     \
                _Pragma("unroll")                                              \
                for (int np = 0; np < 4; np++) {                               \
                    mma_tf32(acc[mt][2*np],   aF[mt], bF[np][0], bF[np][2]);   \
                    mma_tf32(acc[mt][2*np+1], aF[mt], bF[np][1], bF[np][3]);   \
                }                                                              \
        }                                                                      \
    }

    #pragma unroll 1
    for (int kt = 0; kt < NCH; kt += 3) {
        GBODY(kt, 0)
        GBODY(kt + 1, 1)
        GBODY(kt + 2, 2)
    }
#undef GBODY

    size_t zofs = (size_t)bz * ROWS * D_;
    #pragma unroll
    for (int mt = 0; mt < 2; mt++) {
        #pragma unroll
        for (int nt = 0; nt < 8; nt++) {
            int rr = by*128 + wm*32 + mt*16 + (lane >> 2);
            int cc = bx*128 + wn*64 + nt*8 + ((lane & 3) << 1);
            #pragma unroll
            for (int hf = 0; hf < 2; hf++) {
                int r = rr + hf*8;
                float a0 = acc[mt][nt][hf*2], a1 = acc[mt][nt][hf*2 + 1];
                if constexpr (MODE == 4) {
                    *(float2*)(Cf + zofs + (size_t)r*D_ + cc) =
                        make_float2(a0, a1);
                } else if constexpr (MODE == 2) {
                    float v0 = fmaxf(a0 + bias[cc], 0.f);
                    float v1 = fmaxf(a1 + bias[cc + 1], 0.f);
                    *(float2*)(Ct + (size_t)r*ldo + cc) =
                        make_float2(tf32r(v0), tf32r(v1));
                } else {  // MODE 3: QKV
                    float v0 = a0 + bias[cc], v1 = a1 + bias[cc + 1];
                    if (cc < QKN) {
                        *(float2*)(Cf + (size_t)r*QKN + cc) =
                            make_float2(tf32r(v0), tf32r(v1));
                    } else {
                        size_t o = (size_t)r*D_ + (cc - QKN);
                        uint32_t hp, lp; split2(v0, v1, hp, lp);
                        *(uint32_t*)(Ch + o) = hp;
                        *(uint32_t*)(Cl + o) = lp;
                    }
                }
            }
        }
    }
}

// ---------------- fused flash attention: 64-row KV tiles, 2 CTAs/SM ---------
#define QTS 32768                // 128 rows * 256B (Q fp32 tile)
#define KTS 16384                // 64 rows * 256B (K fp32 tile)
#define VTS 9216                 // 64 rows * 144B (V bf16 plane)
#define STKV (KTS + 2*VTS)       // 34816 per stage
#define FSMEM (QTS + 2*STKV + 1024)

__global__ __launch_bounds__(256, 2) void flash_attn(
    const float* __restrict__ qkt,
    const bf16* __restrict__ vh, const bf16* __restrict__ vl,
    const float* __restrict__ relb, float* __restrict__ ct)
{
    extern __shared__ char sm[];
    uint32_t sb = smem_u32(sm);
    float* sbias = (float*)(sm + QTS + 2*STKV);
    int tid = threadIdx.x, lane = tid & 31, wid = tid >> 5;
    int q0 = blockIdx.x * 128;
    int bh = blockIdx.y, b = bh / H_, h = bh % H_;
    size_t rowbase = (size_t)b * S_;
    int hoff = h * DK_;

    for (int i = tid; i < 128*16; i += 256) {
        int r = i >> 4, s = i & 15;
        cpasync16(sb + r*256 + swq(r, s),
                  qkt + (rowbase + q0 + r)*QKN + hoff + s*4);
    }
    auto load_kv = [&](int kt, int st) {
        int k0 = kt << 6;
        uint32_t base = sb + QTS + st*STKV;
        #pragma unroll
        for (int j = 0; j < 4; j++) {
            int i = tid + j*256;
            int r = i >> 4, s = i & 15;
            cpasync16(base + r*256 + swq(r, s),
                      qkt + (rowbase + k0 + r)*QKN + 768 + hoff + s*4);
        }
        #pragma unroll
        for (int j = 0; j < 2; j++) {
            int i = tid + j*256;
            int r = i >> 3, c = i & 7;
            size_t gV = (rowbase + k0 + r)*(size_t)D_ + hoff + c*8;
            uint32_t dst = base + KTS + r*144 + c*16;
            cpasync16(dst, vh + gV);
            cpasync16(dst + VTS, vl + gV);
        }
    };
    load_kv(0, 0);
    asm volatile("cp.async.commit_group;" ::: "memory");

    uint32_t Qf[8][4];
    float accpv[8][4];
    #pragma unroll
    for (int i = 0; i < 8; i++)
        #pragma unroll
        for (int j = 0; j < 4; j++) accpv[i][j] = 0.f;
    float m0 = -1e30f, m1 = -1e30f, l0 = 0.f, l1 = 0.f;
    int r0 = lane >> 2;
    uint32_t half = (uint32_t)(lane >> 4);
    int qrow = wid*16 + (lane & 15);
    int krow0 = lane & 15;
    bool qfrag = false;

    for (int kt = 0; kt < 8; kt++) {
        int st = kt & 1;
        int k0 = kt << 6;
        asm volatile("cp.async.wait_group 0;" ::: "memory");
        __syncthreads();
        if (tid < 191) {
            int ridx = tid + k0 - q0 + 384;
            sbias[tid] = relb[(size_t)ridx * H_ + h];
        }
        if (kt < 7) {
            load_kv(kt + 1, st ^ 1);
            asm volatile("cp.async.commit_group;" ::: "memory");
        }
        if (!qfrag) {
            qfrag = true;
            #pragma unroll
            for (int ks = 0; ks < 8; ks++) {
                uint32_t slot = 2*ks + half;
                ldsm4(Qf[ks], sb + qrow*256 + swq(qrow, slot));
            }
        }
        float sacc[8][4];
        #pragma unroll
        for (int i = 0; i < 8; i++)
            #pragma unroll
            for (int j = 0; j < 4; j++) sacc[i][j] = 0.f;
        uint32_t kbase = sb + QTS + st*STKV;
        #pragma unroll
        for (int ks = 0; ks < 8; ks++) {
            uint32_t slot = 2*ks + half;
            #pragma unroll
            for (int np = 0; np < 4; np++) {
                uint32_t bF[4];
                int kr = np*16 + krow0;
                ldsm4(bF, kbase + kr*256 + swq(kr, slot));
                mma_tf32(sacc[2*np],   Qf[ks], bF[0], bF[2]);
                mma_tf32(sacc[2*np+1], Qf[ks], bF[1], bF[3]);
            }
        }
        __syncthreads();
        int coff = 127 - wid*16;
        float mt0 = -1e30f, mt1 = -1e30f;
        #pragma unroll
        for (int nt = 0; nt < 8; nt++) {
            int col = nt*8 + ((lane & 3) << 1);
            int i0 = col + coff - r0;
            float s0 = fmaf(sacc[nt][0], 0.125f, sbias[i0]);
            float s1 = fmaf(sacc[nt][1], 0.125f, sbias[i0 + 1]);
            float s2 = fmaf(sacc[nt][2], 0.125f, sbias[i0 - 8]);
            float s3 = fmaf(sacc[nt][3], 0.125f, sbias[i0 - 7]);
            sacc[nt][0] = s0; sacc[nt][1] = s1;
            sacc[nt][2] = s2; sacc[nt][3] = s3;
            mt0 = fmaxf(mt0, fmaxf(s0, s1));
            mt1 = fmaxf(mt1, fmaxf(s2, s3));
        }
        #pragma unroll
        for (int o = 1; o < 4; o <<= 1) {
            mt0 = fmaxf(mt0, __shfl_xor_sync(0xffffffffu, mt0, o));
            mt1 = fmaxf(mt1, __shfl_xor_sync(0xffffffffu, mt1, o));
        }
        float mn0 = fmaxf(m0, mt0), mn1 = fmaxf(m1, mt1);
        float cr0 = __expf(m0 - mn0), cr1 = __expf(m1 - mn1);
        m0 = mn0; m1 = mn1;
        float rs0 = 0.f, rs1 = 0.f;
        #pragma unroll
        for (int nt = 0; nt < 8; nt++) {
            float p0 = __expf(sacc[nt][0] - mn0);
            float p1 = __expf(sacc[nt][1] - mn0);
            float p2 = __expf(sacc[nt][2] - mn1);
            float p3 = __expf(sacc[nt][3] - mn1);
            sacc[nt][0] = p0; sacc[nt][1] = p1;
            sacc[nt][2] = p2; sacc[nt][3] = p3;
            rs0 += p0 + p1; rs1 += p2 + p3;
        }
        #pragma unroll
        for (int o = 1; o < 4; o <<= 1) {
            rs0 += __shfl_xor_sync(0xffffffffu, rs0, o);
            rs1 += __shfl_xor_sync(0xffffffffu, rs1, o);
        }
        l0 = l0*cr0 + rs0; l1 = l1*cr1 + rs1;
        #pragma unroll
        for (int nd = 0; nd < 8; nd++) {
            accpv[nd][0] *= cr0; accpv[nd][1] *= cr0;
            accpv[nd][2] *= cr1; accpv[nd][3] *= cr1;
        }
        uint32_t vbase = kbase + KTS;
        uint32_t voff = (uint32_t)((lane & 15)*144) + (half << 4);
        #pragma unroll
        for (int kc2 = 0; kc2 < 4; kc2++) {
            uint32_t Pha[4], Pla[4];
            split2(sacc[2*kc2][0],   sacc[2*kc2][1],   Pha[0], Pla[0]);
            split2(sacc[2*kc2][2],   sacc[2*kc2][3],   Pha[1], Pla[1]);
            split2(sacc[2*kc2+1][0], sacc[2*kc2+1][1], Pha[2], Pla[2]);
            split2(sacc[2*kc2+1][2], sacc[2*kc2+1][3], Pha[3], Pla[3]);
            #pragma unroll
            for (int nd = 0; nd < 4; nd++) {
                uint32_t vh4[4], vl4[4];
                uint32_t va = vbase + kc2*(16*144) + voff + nd*32;
                ldsm4t(vh4, va);
                ldsm4t(vl4, va + VTS);
                mma16816(accpv[2*nd],   Pha, &vh4[0]);
                mma16816(accpv[2*nd+1], Pha, &vh4[2]);
                mma16816(accpv[2*nd],   Pha, &vl4[0]);
                mma16816(accpv[2*nd+1], Pha, &vl4[2]);
                mma16816(accpv[2*nd],   Pla, &vh4[0]);
                mma16816(accpv[2*nd+1], Pla, &vh4[2]);
            }
        }
        __syncthreads();
    }
    float inv0 = 1.f / l0, inv1 = 1.f / l1;
    size_t row = rowbase + q0 + wid*16 + r0;
    #pragma unroll
    for (int nd = 0; nd < 8; nd++) {
        int col = hoff + nd*8 + ((lane & 3) << 1);
        *(float2*)(ct + row*D_ + col) =
            make_float2(tf32r(accpv[nd][0]*inv0), tf32r(accpv[nd][1]*inv0));
        *(float2*)(ct + (row+8)*D_ + col) =
            make_float2(tf32r(accpv[nd][2]*inv1), tf32r(accpv[nd][3]*inv1));
    }
}

// ----- fused split-K reduce + bias + residual + LN (warp per row) -----------
__global__ __launch_bounds__(256) void reduce_ln(
    float* __restrict__ x, const float* __restrict__ part,
    const float* __restrict__ bias,
    const float* __restrict__ g, const float* __restrict__ bb,
    float* __restrict__ xt)
{
    int row = blockIdx.x*8 + (threadIdx.x >> 5);
    int lane = threadIdx.x & 31;
    size_t base = (size_t)row * D_;
    const float* p0 = part + base;
    const float* p1 = part + (size_t)ROWS*D_ + base;
    float v[6][4];
    float s = 0.f;
    #pragma unroll
    for (int i = 0; i < 6; i++) {
        int c = (lane + i*32) * 4;
        float4 a  = *(const float4*)(x + base + c);
        float4 q0 = *(const float4*)(p0 + c);
        float4 q1 = *(const float4*)(p1 + c);
        float4 bv = *(const float4*)(bias + c);
        v[i][0] = a.x + q0.x + q1.x + bv.x;
        v[i][1] = a.y + q0.y + q1.y + bv.y;
        v[i][2] = a.z + q0.z + q1.z + bv.z;
        v[i][3] = a.w + q0.w + q1.w + bv.w;
        s += v[i][0] + v[i][1] + v[i][2] + v[i][3];
    }
    #pragma unroll
    for (int o = 16; o; o >>= 1) s += __shfl_xor_sync(0xffffffffu, s, o);
    float mean = s * (1.f/(float)D_);
    float ss = 0.f;
    #pragma unroll
    for (int i = 0; i < 6; i++)
        #pragma unroll
        for (int j = 0; j < 4; j++) { float d = v[i][j]-mean; ss += d*d; }
    #pragma unroll
    for (int o = 16; o; o >>= 1) ss += __shfl_xor_sync(0xffffffffu, ss, o);
    float rstd = rsqrtf(ss * (1.f/(float)D_) + 1e-5f);
    #pragma unroll
    for (int i = 0; i < 6; i++) {
        int c = (lane + i*32) * 4;
        float4 gg = *(const float4*)(g + c);
        float4 bv = *(const float4*)(bb + c);
        float o0 = (v[i][0]-mean)*rstd*gg.x + bv.x;
        float o1 = (v[i][1]-mean)*rstd*gg.y + bv.y;
        float o2 = (v[i][2]-mean)*rstd*gg.z + bv.z;
        float o3 = (v[i][3]-mean)*rstd*gg.w + bv.w;
        *(float4*)(x + base + c)  = make_float4(o0, o1, o2, o3);
        *(float4*)(xt + base + c) = make_float4(tf32r(o0), tf32r(o1),
                                                tf32r(o2), tf32r(o3));
    }
}

// ---------------- head ------------------------------------------------------
__global__ __launch_bounds__(256) void meanpool(
    const float* __restrict__ x, float* __restrict__ pool)
{
    int d = blockIdx.x*256 + threadIdx.x;
    int b = blockIdx.y;
    float s = 0.f;
    for (int t = 0; t < S_; t++) s += x[((size_t)b*S_ + t)*D_ + d];
    pool[b*D_ + d] = s * (1.f/(float)S_);
}
__global__ __launch_bounds__(256) void fc1(
    const float* __restrict__ pool, const float* __restrict__ w,
    const float* __restrict__ bias, float* __restrict__ out)
{
    int idx = blockIdx.x*256 + threadIdx.x;
    int b = idx / (D_/2), j = idx % (D_/2);
    float s = bias[j];
    for (int d = 0; d < D_; d++) s = fmaf(pool[b*D_ + d], w[d*(D_/2) + j], s);
    out[idx] = fmaxf(s, 0.f);
}
__global__ __launch_bounds__(256) void fc2(
    const float* __restrict__ h, const float* __restrict__ w,
    const float* __restrict__ bias, float* __restrict__ out)
{
    int idx = blockIdx.x*256 + threadIdx.x;
    if (idx >= B_*NC_) return;
    int b = idx / NC_, c = idx % NC_;
    float s = bias[c];
    for (int j = 0; j < D_/2; j++) s = fmaf(h[b*(D_/2) + j], w[j*NC_ + c], s);
    out[idx] = s;
}

// ---------------- launch ----------------------------------------------------
extern "C" void kernel_launch(void* const* d_in, const int* in_sizes, int n_in,
                              void* d_out, int out_size)
{
    const int*   ids  = (const int*)  d_in[0];
    const float* emb  = (const float*)d_in[1];
    const float* wq   = (const float*)d_in[2];
    const float* bq   = (const float*)d_in[3];
    const float* wk   = (const float*)d_in[4];
    const float* bk   = (const float*)d_in[5];
    const float* wv   = (const float*)d_in[6];
    const float* bv   = (const float*)d_in[7];
    const float* wo   = (const float*)d_in[8];
    const float* bo   = (const float*)d_in[9];
    const float* relb = (const float*)d_in[10];
    const float* w1   = (const float*)d_in[11];
    const float* b1   = (const float*)d_in[12];
    const float* w2   = (const float*)d_in[13];
    const float* b2   = (const float*)d_in[14];
    const float* l1g  = (const float*)d_in[15];
    const float* l1b  = (const float*)d_in[16];
    const float* l2g  = (const float*)d_in[17];
    const float* l2b  = (const float*)d_in[18];
    const float* cw1  = (const float*)d_in[19];
    const float* cb1  = (const float*)d_in[20];
    const float* cw2  = (const float*)d_in[21];
    const float* cb2  = (const float*)d_in[22];

    cudaFuncSetAttribute(gemm_tf32<24,2>, cudaFuncAttributeMaxDynamicSharedMemorySize, GSMEM);
    cudaFuncSetAttribute(gemm_tf32<24,3>, cudaFuncAttributeMaxDynamicSharedMemorySize, GSMEM);
    cudaFuncSetAttribute(gemm_tf32<12,4>, cudaFuncAttributeMaxDynamicSharedMemorySize, GSMEM);
    cudaFuncSetAttribute(gemm_tf32<48,4>, cudaFuncAttributeMaxDynamicSharedMemorySize, GSMEM);
    cudaFuncSetAttribute(flash_attn, cudaFuncAttributeMaxDynamicSharedMemorySize, FSMEM);

    float *x, *xt, *part, *qkt, *ct, *ft, *pool, *chd, *bqkv;
    float *wqkvt, *wot, *w1t, *w2t;
    bf16 *vhp, *vlp;
    cudaGetSymbolAddress((void**)&x,    g_x);
    cudaGetSymbolAddress((void**)&xt,   g_xt);
    cudaGetSymbolAddress((void**)&part, g_part);
    cudaGetSymbolAddress((void**)&qkt,  g_qkt);
    cudaGetSymbolAddress((void**)&ct,   g_ct);
    cudaGetSymbolAddress((void**)&ft,   g_ft);
    cudaGetSymbolAddress((void**)&pool, g_pool);
    cudaGetSymbolAddress((void**)&chd,  g_chd);
    cudaGetSymbolAddress((void**)&bqkv, g_bqkv);
    cudaGetSymbolAddress((void**)&vhp,  g_vh);
    cudaGetSymbolAddress((void**)&vlp,  g_vl);
    cudaGetSymbolAddress((void**)&wqkvt,g_wqkvt);
    cudaGetSymbolAddress((void**)&wot,  g_wot);
    cudaGetSymbolAddress((void**)&w1t,  g_w1t);
    cudaGetSymbolAddress((void**)&w2t,  g_w2t);

    embed_kernel<<<ROWS, 256>>>(ids, emb, x, xt);
    wprep_qkv3<<<dim3(D_/32, D_/32, L_*3), 256>>>(wq, wk, wv, wqkvt);
    wprep_rest<<<dim3(5185, L_), 256>>>(wo, w1, w2, bq, bk, bv,
        wot, w1t, w2t, bqkv);

    dim3 gQKV(QKVN/128, ROWS/128);
    dim3 gSK(D_/128, ROWS/128, 2);     // split-K grids: 768 CTAs
    dim3 gF1(DFF_/128, ROWS/128);

    for (int l = 0; l < L_; l++) {
        gemm_tf32<24,3><<<gQKV, 256, GSMEM>>>(xt, D_,
            wqkvt + (size_t)l*QKVN*D_, D_,
            bqkv + (size_t)l*QKVN, qkt, vhp, vlp, nullptr, QKN);

        flash_attn<<<dim3(S_/128, BH_), 256, FSMEM>>>(
            qkt, vhp, vlp, relb + (size_t)l*(2*S_-1)*H_, ct);

        gemm_tf32<12,4><<<gSK, 256, GSMEM>>>(ct, D_,
            wot + (size_t)l*D_*D_, D_,
            nullptr, part, nullptr, nullptr, nullptr, D_);
        reduce_ln<<<ROWS/8, 256>>>(x, part, bo + l*D_,
            l1g + l*D_, l1b + l*D_, xt);

        gemm_tf32<24,2><<<gF1, 256, GSMEM>>>(xt, D_,
            w1t + (size_t)l*D_*DFF_, D_,
            b1 + l*DFF_, nullptr, nullptr, nullptr, ft, DFF_);
        gemm_tf32<48,4><<<gSK, 256, GSMEM>>>(ft, DFF_,
            w2t + (size_t)l*DFF_*D_, DFF_,
            nullptr, part, nullptr, nullptr, nullptr, D_);
        reduce_ln<<<ROWS/8, 256>>>(x, part, b2 + l*D_,
            l2g + l*D_, l2b + l*D_, xt);
    }

    meanpool<<<dim3(D_/256, B_), 256>>>(x, pool);
    fc1<<<(B_*(D_/2))/256, 256>>>(pool, cw1, cb1, chd);
    fc2<<<(B_*NC_ + 255)/256, 256>>>(chd, cw2, cb2, (float*)d_out);
}

// round 17
// speedup vs baseline: 1.0085x; 1.0085x over previous
#include <cuda_runtime.h>
#include <cuda_bf16.h>
#include <cstdint>
#include <cstddef>

#define D_    768
#define H_    12
#define DK_   64
#define DFF_  3072
#define L_    12
#define NC_   100
#define S_    512
#define B_    16
#define ROWS  (B_*S_)          // 8192
#define BH_   (B_*H_)          // 192
#define QKVN  2304
#define QKN   1536

typedef __nv_bfloat16 bf16;

// ---------------- scratch (static device globals; no allocation) ----------
__device__ __align__(256) float g_x   [ROWS*(size_t)D_];
__device__ __align__(256) float g_t   [ROWS*(size_t)D_];
__device__ __align__(256) float g_xt  [ROWS*(size_t)D_];
__device__ __align__(256) float g_qkt [ROWS*(size_t)QKN];
__device__ __align__(256) bf16  g_vh  [ROWS*(size_t)D_];
__device__ __align__(256) bf16  g_vl  [ROWS*(size_t)D_];
__device__ __align__(256) float g_ct  [ROWS*(size_t)D_];
__device__ __align__(256) float g_ft  [ROWS*(size_t)DFF_];
__device__ __align__(256) float g_wqkvt[(size_t)L_*QKVN*D_];
__device__ __align__(256) float g_wot [(size_t)L_*D_*D_];
__device__ __align__(256) float g_w1t [(size_t)L_*DFF_*D_];
__device__ __align__(256) float g_w2t [(size_t)L_*DFF_*D_];
__device__ __align__(256) float g_bqkv[(size_t)L_*QKVN];
__device__ __align__(256) float g_pool[B_*D_];
__device__ __align__(256) float g_chd [B_*(D_/2)];

// ---------------- helpers ---------------------------------------------------
__device__ __forceinline__ uint32_t smem_u32(const void* p) {
    uint32_t a;
    asm("{ .reg .u64 t; cvta.to.shared.u64 t, %1; cvt.u32.u64 %0, t; }" : "=r"(a) : "l"(p));
    return a;
}
__device__ __forceinline__ float tf32r(float v) {
    uint32_t o; asm("cvt.rna.tf32.f32 %0, %1;" : "=r"(o) : "f"(v));
    return __uint_as_float(o);
}
__device__ __forceinline__ void split_bf16(float v, bf16& h, bf16& l) {
    h = __float2bfloat16(v);
    l = __float2bfloat16(v - __bfloat162float(h));
}
__device__ __forceinline__ void split2(float a, float b, uint32_t& hp, uint32_t& lp) {
    bf16 h0, l0, h1, l1;
    split_bf16(a, h0, l0); split_bf16(b, h1, l1);
    __nv_bfloat162 hv; hv.x = h0; hv.y = h1;
    __nv_bfloat162 lv; lv.x = l0; lv.y = l1;
    hp = *(uint32_t*)&hv; lp = *(uint32_t*)&lv;
}
__device__ __forceinline__ void ldsm4(uint32_t* r, uint32_t a) {
    asm volatile("ldmatrix.sync.aligned.m8n8.x4.shared.b16 {%0,%1,%2,%3}, [%4];"
        : "=r"(r[0]), "=r"(r[1]), "=r"(r[2]), "=r"(r[3]) : "r"(a));
}
__device__ __forceinline__ void ldsm4t(uint32_t* r, uint32_t a) {
    asm volatile("ldmatrix.sync.aligned.m8n8.x4.trans.shared.b16 {%0,%1,%2,%3}, [%4];"
        : "=r"(r[0]), "=r"(r[1]), "=r"(r[2]), "=r"(r[3]) : "r"(a));
}
__device__ __forceinline__ void mma16816(float* c, const uint32_t* a, const uint32_t* b) {
    asm volatile("mma.sync.aligned.m16n8k16.row.col.f32.bf16.bf16.f32 "
        "{%0,%1,%2,%3}, {%4,%5,%6,%7}, {%8,%9}, {%0,%1,%2,%3};"
        : "+f"(c[0]), "+f"(c[1]), "+f"(c[2]), "+f"(c[3])
        : "r"(a[0]), "r"(a[1]), "r"(a[2]), "r"(a[3]), "r"(b[0]), "r"(b[1]));
}
__device__ __forceinline__ void mma_tf32(float* c, const uint32_t* a, uint32_t b0, uint32_t b1) {
    asm volatile("mma.sync.aligned.m16n8k8.row.col.f32.tf32.tf32.f32 "
        "{%0,%1,%2,%3}, {%4,%5,%6,%7}, {%8,%9}, {%0,%1,%2,%3};"
        : "+f"(c[0]), "+f"(c[1]), "+f"(c[2]), "+f"(c[3])
        : "r"(a[0]), "r"(a[1]), "r"(a[2]), "r"(a[3]), "r"(b0), "r"(b1));
}
__device__ __forceinline__ void cpasync16(uint32_t dst, const void* src) {
    asm volatile("cp.async.cg.shared.global [%0], [%1], 16;" :: "r"(dst), "l"(src));
}
__device__ __forceinline__ uint32_t swq(int r, int s) {
    return (uint32_t)(((s & 8) | ((s ^ r) & 7)) << 4);
}

// ---------------- embedding + PE -------------------------------------------
__global__ __launch_bounds__(256) void embed_kernel(
    const int* __restrict__ ids, const float* __restrict__ emb,
    float* __restrict__ x, float* __restrict__ xt)
{
    int row = blockIdx.x;
    int s   = row & (S_-1);
    int tok = ids[row];
    size_t base = (size_t)row * D_;
    const float NEG = -9.210340371976184f / (float)D_;
    #pragma unroll
    for (int i = 0; i < 3; i++) {
        int d = threadIdx.x + i*256;
        int k2 = (d >> 1) << 1;
        float ang = (float)s * __expf((float)k2 * NEG);
        float pe  = (d & 1) ? cosf(ang) : sinf(ang);
        float v = emb[(size_t)tok * D_ + d] + pe;
        x[base + d] = v;
        xt[base + d] = tf32r(v);
    }
}

// ---------------- weight prep -----------------------------------------------
__global__ __launch_bounds__(256) void wprep_qkv3(
    const float* __restrict__ Wq, const float* __restrict__ Wk,
    const float* __restrict__ Wv, float* __restrict__ Tt)
{
    __shared__ float t[32][33];
    int tx = threadIdx.x & 31, ty = threadIdx.x >> 5;
    int n0 = blockIdx.x * 32, k0 = blockIdx.y * 32;
    int z = blockIdx.z, l = z / 3, m = z % 3;
    const float* W = (m == 0 ? Wq : m == 1 ? Wk : Wv) + (size_t)l * D_ * D_;
    size_t obase = (size_t)z * D_ * D_;
    #pragma unroll
    for (int i = ty; i < 32; i += 8)
        t[i][tx] = W[(size_t)(k0 + i) * D_ + n0 + tx];
    __syncthreads();
    #pragma unroll
    for (int i = ty; i < 32; i += 8)
        Tt[obase + (size_t)(n0 + i) * D_ + k0 + tx] = tf32r(t[tx][i]);
}

__global__ __launch_bounds__(256) void wprep_rest(
    const float* __restrict__ wo, const float* __restrict__ w1,
    const float* __restrict__ w2,
    const float* __restrict__ bq, const float* __restrict__ bk,
    const float* __restrict__ bv,
    float* __restrict__ wot, float* __restrict__ w1t, float* __restrict__ w2t,
    float* __restrict__ bqkv)
{
    int bx = blockIdx.x, l = blockIdx.y;
    if (bx >= 5184) {
        for (int j = threadIdx.x; j < QKVN; j += 256) {
            float v = (j < 768) ? bq[l*768 + j]
                    : (j < 1536) ? bk[l*768 + j - 768]
                                 : bv[l*768 + j - 1536];
            bqkv[(size_t)l*QKVN + j] = v;
        }
        return;
    }
    __shared__ float t[32][33];
    int tx = threadIdx.x & 31, ty = threadIdx.x >> 5;
    const float* W; float* Tt; int K, N, n0, k0;
    if (bx < 576) {
        K = D_; N = D_;  n0 = (bx % 24)*32; k0 = (bx / 24)*32;
        W = wo + (size_t)l*D_*D_;  Tt = wot + (size_t)l*D_*D_;
    } else if (bx < 2880) {
        int i = bx - 576;
        K = D_; N = DFF_; n0 = (i % 96)*32; k0 = (i / 96)*32;
        W = w1 + (size_t)l*D_*DFF_; Tt = w1t + (size_t)l*D_*DFF_;
    } else {
        int i = bx - 2880;
        K = DFF_; N = D_; n0 = (i % 24)*32; k0 = (i / 24)*32;
        W = w2 + (size_t)l*DFF_*D_; Tt = w2t + (size_t)l*DFF_*D_;
    }
    #pragma unroll
    for (int i = ty; i < 32; i += 8)
        t[i][tx] = W[(size_t)(k0 + i) * N + n0 + tx];
    __syncthreads();
    #pragma unroll
    for (int i = ty; i < 32; i += 8)
        Tt[(size_t)(n0 + i) * K + k0 + tx] = tf32r(t[tx][i]);
}

// ---------------- tf32 warp-MMA GEMM (8 warps x 32x64) ----------------------
// MODE: 0 fp32+bias->Cf | 2 bias+relu+tf32->Ct | 3 qkv (Q prescaled 1/8)
#define TILEF 16384           // 128 rows * 128B
#define BUFF  32768           // A + B per stage
#define GSMEM (3*BUFF)        // 98304; x2 CTAs = 192KB

template<int NCH, int MODE>
__global__ __launch_bounds__(256, 2) void gemm_tf32(
    const float* __restrict__ A, int lda,
    const float* __restrict__ Bt, int ldb,
    const float* __restrict__ bias,
    float* __restrict__ Cf, bf16* __restrict__ Ch, bf16* __restrict__ Cl,
    float* __restrict__ Ct, int ldo)
{
    extern __shared__ char smx[];
    uint32_t sb = smem_u32(smx);
    int tid = threadIdx.x, lane = tid & 31, wid = tid >> 5;
    int bx = blockIdx.x, by = blockIdx.y;
    int wm = wid & 3, wn = wid >> 2;

    float acc[2][8][4];
    #pragma unroll
    for (int i = 0; i < 2; i++)
        #pragma unroll
        for (int j = 0; j < 8; j++)
            #pragma unroll
            for (int q = 0; q < 4; q++) acc[i][j][q] = 0.f;

    int r0 = tid >> 3, s0 = tid & 7;
    const float* srcA = A  + (size_t)(by*128 + r0)*lda + s0*4;
    const float* srcB = Bt + (size_t)(bx*128 + r0)*ldb + s0*4;
    uint32_t dstoff = (uint32_t)(r0*128 + ((s0 ^ (r0 & 7)) << 4));
    size_t stepA = (size_t)32*lda, stepB = (size_t)32*ldb;

    int arow = wm*32 + (lane & 15);
    int brow = wn*64 + (lane & 15);
    uint32_t half = (uint32_t)(lane >> 4);
    uint32_t aR = (uint32_t)arow*128, bR = (uint32_t)brow*128;
    uint32_t ax = (uint32_t)(arow & 7), bxr = (uint32_t)(brow & 7);

    auto loadc = [&](uint32_t dbase) {
        #pragma unroll
        for (int j = 0; j < 4; j++)
            cpasync16(dbase + dstoff + j*4096, srcA + j*stepA);
        #pragma unroll
        for (int j = 0; j < 4; j++)
            cpasync16(dbase + TILEF + dstoff + j*4096, srcB + j*stepB);
        asm volatile("cp.async.commit_group;" ::: "memory");
        srcA += 32; srcB += 32;
    };

    loadc(sb);
    loadc(sb + BUFF);

#define GBODY(KT, ST)                                                          \
    {                                                                          \
        if ((KT) + 1 < NCH) asm volatile("cp.async.wait_group 1;" ::: "memory"); \
        else                asm volatile("cp.async.wait_group 0;" ::: "memory"); \
        __syncthreads();                                                       \
        if ((KT) + 2 < NCH) loadc(sb + (((ST) + 2) % 3)*BUFF);                 \
        uint32_t abase = sb + (ST)*BUFF;                                       \
        uint32_t bbase = abase + TILEF;                                        \
        _Pragma("unroll")                                                      \
        for (int ks = 0; ks < 4; ks++) {                                       \
            uint32_t slot = 2*ks + half;                                       \
            uint32_t aF[2][4], bF[4][4];                                       \
            _Pragma("unroll")                                                  \
            for (int mt = 0; mt < 2; mt++)                                     \
                ldsm4(aF[mt], abase + aR + mt*2048 + ((slot ^ ax) << 4));      \
            _Pragma("unroll")                                                  \
            for (int np = 0; np < 4; np++)                                     \
                ldsm4(bF[np], bbase + bR + np*2048 + ((slot ^ bxr) << 4));     \
            _Pragma("unroll")                                                  \
            for (int mt = 0; mt < 2; mt++)                                     \
                _Pragma("unroll")                                              \
                for (int np = 0; np < 4; np++) {                               \
                    mma_tf32(acc[mt][2*np],   aF[mt], bF[np][0], bF[np][2]);   \
                    mma_tf32(acc[mt][2*np+1], aF[mt], bF[np][1], bF[np][3]);   \
                }                                                              \
        }                                                                      \
    }

    #pragma unroll 1
    for (int kt = 0; kt < NCH; kt += 3) {
        GBODY(kt, 0)
        GBODY(kt + 1, 1)
        GBODY(kt + 2, 2)
    }
#undef GBODY

    #pragma unroll
    for (int mt = 0; mt < 2; mt++) {
        #pragma unroll
        for (int nt = 0; nt < 8; nt++) {
            int rr = by*128 + wm*32 + mt*16 + (lane >> 2);
            int cc = bx*128 + wn*64 + nt*8 + ((lane & 3) << 1);
            #pragma unroll
            for (int hf = 0; hf < 2; hf++) {
                int r = rr + hf*8;
                float v0 = acc[mt][nt][hf*2] + bias[cc];
                float v1 = acc[mt][nt][hf*2 + 1] + bias[cc + 1];
                if constexpr (MODE == 0) {
                    *(float2*)(Cf + (size_t)r*ldo + cc) = make_float2(v0, v1);
                } else if constexpr (MODE == 2) {
                    v0 = fmaxf(v0, 0.f); v1 = fmaxf(v1, 0.f);
                    *(float2*)(Ct + (size_t)r*ldo + cc) =
                        make_float2(tf32r(v0), tf32r(v1));
                } else {  // MODE 3: QKV; Q gets prescaled by 1/8 for attention
                    if (cc < QKN) {
                        float sc = (cc < D_) ? 0.125f : 1.0f;
                        *(float2*)(Cf + (size_t)r*QKN + cc) =
                            make_float2(tf32r(v0*sc), tf32r(v1*sc));
                    } else {
                        size_t o = (size_t)r*D_ + (cc - QKN);
                        uint32_t hp, lp; split2(v0, v1, hp, lp);
                        *(uint32_t*)(Ch + o) = hp;
                        *(uint32_t*)(Cl + o) = lp;
                    }
                }
            }
        }
    }
}

// ---------------- fused flash attention: 64-row KV tiles, 2 CTAs/SM ---------
#define QTS 32768                // 128 rows * 256B (Q fp32 tile)
#define KTS 16384                // 64 rows * 256B (K fp32 tile)
#define VTS 9216                 // 64 rows * 144B (V bf16 plane)
#define STKV (KTS + 2*VTS)       // 34816 per stage
#define FSMEM (QTS + 2*STKV + 1024)

__global__ __launch_bounds__(256, 2) void flash_attn(
    const float* __restrict__ qkt,
    const bf16* __restrict__ vh, const bf16* __restrict__ vl,
    const float* __restrict__ relb, float* __restrict__ ct)
{
    extern __shared__ char sm[];
    uint32_t sb = smem_u32(sm);
    float* sbias = (float*)(sm + QTS + 2*STKV);
    int tid = threadIdx.x, lane = tid & 31, wid = tid >> 5;
    int q0 = blockIdx.x * 128;
    int bh = blockIdx.y, b = bh / H_, h = bh % H_;
    size_t rowbase = (size_t)b * S_;
    int hoff = h * DK_;

    for (int i = tid; i < 128*16; i += 256) {
        int r = i >> 4, s = i & 15;
        cpasync16(sb + r*256 + swq(r, s),
                  qkt + (rowbase + q0 + r)*QKN + hoff + s*4);
    }
    auto load_kv = [&](int kt, int st) {
        int k0 = kt << 6;
        uint32_t base = sb + QTS + st*STKV;
        #pragma unroll
        for (int j = 0; j < 4; j++) {
            int i = tid + j*256;
            int r = i >> 4, s = i & 15;
            cpasync16(base + r*256 + swq(r, s),
                      qkt + (rowbase + k0 + r)*QKN + 768 + hoff + s*4);
        }
        #pragma unroll
        for (int j = 0; j < 2; j++) {
            int i = tid + j*256;
            int r = i >> 3, c = i & 7;
            size_t gV = (rowbase + k0 + r)*(size_t)D_ + hoff + c*8;
            uint32_t dst = base + KTS + r*144 + c*16;
            cpasync16(dst, vh + gV);
            cpasync16(dst + VTS, vl + gV);
        }
    };
    load_kv(0, 0);
    asm volatile("cp.async.commit_group;" ::: "memory");

    uint32_t Qf[8][4];
    float accpv[8][4];
    #pragma unroll
    for (int i = 0; i < 8; i++)
        #pragma unroll
        for (int j = 0; j < 4; j++) accpv[i][j] = 0.f;
    float m0 = -1e30f, m1 = -1e30f, l0 = 0.f, l1 = 0.f;
    int r0 = lane >> 2;
    uint32_t half = (uint32_t)(lane >> 4);
    int qrow = wid*16 + (lane & 15);
    int krow0 = lane & 15;
    bool qfrag = false;

    for (int kt = 0; kt < 8; kt++) {
        int st = kt & 1;
        int k0 = kt << 6;
        asm volatile("cp.async.wait_group 0;" ::: "memory");
        __syncthreads();
        if (tid < 191) {
            int ridx = tid + k0 - q0 + 384;
            sbias[tid] = relb[(size_t)ridx * H_ + h];
        }
        if (kt < 7) {
            load_kv(kt + 1, st ^ 1);
            asm volatile("cp.async.commit_group;" ::: "memory");
        }
        if (!qfrag) {
            qfrag = true;
            #pragma unroll
            for (int ks = 0; ks < 8; ks++) {
                uint32_t slot = 2*ks + half;
                ldsm4(Qf[ks], sb + qrow*256 + swq(qrow, slot));
            }
        }
        float sacc[8][4];
        #pragma unroll
        for (int i = 0; i < 8; i++)
            #pragma unroll
            for (int j = 0; j < 4; j++) sacc[i][j] = 0.f;
        uint32_t kbase = sb + QTS + st*STKV;
        #pragma unroll
        for (int ks = 0; ks < 8; ks++) {
            uint32_t slot = 2*ks + half;
            #pragma unroll
            for (int np = 0; np < 4; np++) {
                uint32_t bF[4];
                int kr = np*16 + krow0;
                ldsm4(bF, kbase + kr*256 + swq(kr, slot));
                mma_tf32(sacc[2*np],   Qf[ks], bF[0], bF[2]);
                mma_tf32(sacc[2*np+1], Qf[ks], bF[1], bF[3]);
            }
        }
        __syncthreads();
        // ---- bias + online softmax (Q already prescaled by 1/8) ----
        int coff = 127 - wid*16;
        float mt0 = -1e30f, mt1 = -1e30f;
        #pragma unroll
        for (int nt = 0; nt < 8; nt++) {
            int col = nt*8 + ((lane & 3) << 1);
            int i0 = col + coff - r0;
            float s0 = sacc[nt][0] + sbias[i0];
            float s1 = sacc[nt][1] + sbias[i0 + 1];
            float s2 = sacc[nt][2] + sbias[i0 - 8];
            float s3 = sacc[nt][3] + sbias[i0 - 7];
            sacc[nt][0] = s0; sacc[nt][1] = s1;
            sacc[nt][2] = s2; sacc[nt][3] = s3;
            mt0 = fmaxf(mt0, fmaxf(s0, s1));
            mt1 = fmaxf(mt1, fmaxf(s2, s3));
        }
        #pragma unroll
        for (int o = 1; o < 4; o <<= 1) {
            mt0 = fmaxf(mt0, __shfl_xor_sync(0xffffffffu, mt0, o));
            mt1 = fmaxf(mt1, __shfl_xor_sync(0xffffffffu, mt1, o));
        }
        float mn0 = fmaxf(m0, mt0), mn1 = fmaxf(m1, mt1);
        float cr0 = __expf(m0 - mn0), cr1 = __expf(m1 - mn1);
        m0 = mn0; m1 = mn1;
        float rs0 = 0.f, rs1 = 0.f;
        #pragma unroll
        for (int nt = 0; nt < 8; nt++) {
            float p0 = __expf(sacc[nt][0] - mn0);
            float p1 = __expf(sacc[nt][1] - mn0);
            float p2 = __expf(sacc[nt][2] - mn1);
            float p3 = __expf(sacc[nt][3] - mn1);
            sacc[nt][0] = p0; sacc[nt][1] = p1;
            sacc[nt][2] = p2; sacc[nt][3] = p3;
            rs0 += p0 + p1; rs1 += p2 + p3;
        }
        #pragma unroll
        for (int o = 1; o < 4; o <<= 1) {
            rs0 += __shfl_xor_sync(0xffffffffu, rs0, o);
            rs1 += __shfl_xor_sync(0xffffffffu, rs1, o);
        }
        l0 = l0*cr0 + rs0; l1 = l1*cr1 + rs1;
        #pragma unroll
        for (int nd = 0; nd < 8; nd++) {
            accpv[nd][0] *= cr0; accpv[nd][1] *= cr0;
            accpv[nd][2] *= cr1; accpv[nd][3] *= cr1;
        }
        uint32_t vbase = kbase + KTS;
        uint32_t voff = (uint32_t)((lane & 15)*144) + (half << 4);
        #pragma unroll
        for (int kc2 = 0; kc2 < 4; kc2++) {
            uint32_t Pha[4], Pla[4];
            split2(sacc[2*kc2][0],   sacc[2*kc2][1],   Pha[0], Pla[0]);
            split2(sacc[2*kc2][2],   sacc[2*kc2][3],   Pha[1], Pla[1]);
            split2(sacc[2*kc2+1][0], sacc[2*kc2+1][1], Pha[2], Pla[2]);
            split2(sacc[2*kc2+1][2], sacc[2*kc2+1][3], Pha[3], Pla[3]);
            #pragma unroll
            for (int nd = 0; nd < 4; nd++) {
                uint32_t vh4[4], vl4[4];
                uint32_t va = vbase + kc2*(16*144) + voff + nd*32;
                ldsm4t(vh4, va);
                ldsm4t(vl4, va + VTS);
                mma16816(accpv[2*nd],   Pha, &vh4[0]);
                mma16816(accpv[2*nd+1], Pha, &vh4[2]);
                mma16816(accpv[2*nd],   Pha, &vl4[0]);
                mma16816(accpv[2*nd+1], Pha, &vl4[2]);
                mma16816(accpv[2*nd],   Pla, &vh4[0]);
                mma16816(accpv[2*nd+1], Pla, &vh4[2]);
            }
        }
        __syncthreads();
    }
    float inv0 = 1.f / l0, inv1 = 1.f / l1;
    size_t row = rowbase + q0 + wid*16 + r0;
    #pragma unroll
    for (int nd = 0; nd < 8; nd++) {
        int col = hoff + nd*8 + ((lane & 3) << 1);
        *(float2*)(ct + row*D_ + col) =
            make_float2(tf32r(accpv[nd][0]*inv0), tf32r(accpv[nd][1]*inv0));
        *(float2*)(ct + (row+8)*D_ + col) =
            make_float2(tf32r(accpv[nd][2]*inv1), tf32r(accpv[nd][3]*inv1));
    }
}

// ---------------- add+LN: one warp per row ----------------------------------
__global__ __launch_bounds__(256) void add_ln(
    float* __restrict__ x, const float* __restrict__ t,
    const float* __restrict__ g, const float* __restrict__ bb,
    float* __restrict__ xt)
{
    int row = blockIdx.x*8 + (threadIdx.x >> 5);
    int lane = threadIdx.x & 31;
    size_t base = (size_t)row * D_;
    float v[6][4];
    float s = 0.f;
    #pragma unroll
    for (int i = 0; i < 6; i++) {
        int c = (lane + i*32) * 4;
        float4 a = *(const float4*)(x + base + c);
        float4 d = *(const float4*)(t + base + c);
        v[i][0] = a.x + d.x; v[i][1] = a.y + d.y;
        v[i][2] = a.z + d.z; v[i][3] = a.w + d.w;
        s += v[i][0] + v[i][1] + v[i][2] + v[i][3];
    }
    #pragma unroll
    for (int o = 16; o; o >>= 1) s += __shfl_xor_sync(0xffffffffu, s, o);
    float mean = s * (1.f/(float)D_);
    float ss = 0.f;
    #pragma unroll
    for (int i = 0; i < 6; i++)
        #pragma unroll
        for (int j = 0; j < 4; j++) { float d = v[i][j]-mean; ss += d*d; }
    #pragma unroll
    for (int o = 16; o; o >>= 1) ss += __shfl_xor_sync(0xffffffffu, ss, o);
    float rstd = rsqrtf(ss * (1.f/(float)D_) + 1e-5f);
    #pragma unroll
    for (int i = 0; i < 6; i++) {
        int c = (lane + i*32) * 4;
        float4 gg = *(const float4*)(g + c);
        float4 bv = *(const float4*)(bb + c);
        float o0 = (v[i][0]-mean)*rstd*gg.x + bv.x;
        float o1 = (v[i][1]-mean)*rstd*gg.y + bv.y;
        float o2 = (v[i][2]-mean)*rstd*gg.z + bv.z;
        float o3 = (v[i][3]-mean)*rstd*gg.w + bv.w;
        *(float4*)(x + base + c)  = make_float4(o0, o1, o2, o3);
        *(float4*)(xt + base + c) = make_float4(tf32r(o0), tf32r(o1),
                                                tf32r(o2), tf32r(o3));
    }
}

// ---------------- head ------------------------------------------------------
__global__ __launch_bounds__(256) void meanpool(
    const float* __restrict__ x, float* __restrict__ pool)
{
    int d = blockIdx.x*256 + threadIdx.x;
    int b = blockIdx.y;
    float s = 0.f;
    for (int t = 0; t < S_; t++) s += x[((size_t)b*S_ + t)*D_ + d];
    pool[b*D_ + d] = s * (1.f/(float)S_);
}
__global__ __launch_bounds__(256) void fc1(
    const float* __restrict__ pool, const float* __restrict__ w,
    const float* __restrict__ bias, float* __restrict__ out)
{
    int idx = blockIdx.x*256 + threadIdx.x;
    int b = idx / (D_/2), j = idx % (D_/2);
    float s = bias[j];
    for (int d = 0; d < D_; d++) s = fmaf(pool[b*D_ + d], w[d*(D_/2) + j], s);
    out[idx] = fmaxf(s, 0.f);
}
__global__ __launch_bounds__(256) void fc2(
    const float* __restrict__ h, const float* __restrict__ w,
    const float* __restrict__ bias, float* __restrict__ out)
{
    int idx = blockIdx.x*256 + threadIdx.x;
    if (idx >= B_*NC_) return;
    int b = idx / NC_, c = idx % NC_;
    float s = bias[c];
    for (int j = 0; j < D_/2; j++) s = fmaf(h[b*(D_/2) + j], w[j*NC_ + c], s);
    out[idx] = s;
}

// ---------------- launch ----------------------------------------------------
extern "C" void kernel_launch(void* const* d_in, const int* in_sizes, int n_in,
                              void* d_out, int out_size)
{
    const int*   ids  = (const int*)  d_in[0];
    const float* emb  = (const float*)d_in[1];
    const float* wq   = (const float*)d_in[2];
    const float* bq   = (const float*)d_in[3];
    const float* wk   = (const float*)d_in[4];
    const float* bk   = (const float*)d_in[5];
    const float* wv   = (const float*)d_in[6];
    const float* bv   = (const float*)d_in[7];
    const float* wo   = (const float*)d_in[8];
    const float* bo   = (const float*)d_in[9];
    const float* relb = (const float*)d_in[10];
    const float* w1   = (const float*)d_in[11];
    const float* b1   = (const float*)d_in[12];
    const float* w2   = (const float*)d_in[13];
    const float* b2   = (const float*)d_in[14];
    const float* l1g  = (const float*)d_in[15];
    const float* l1b  = (const float*)d_in[16];
    const float* l2g  = (const float*)d_in[17];
    const float* l2b  = (const float*)d_in[18];
    const float* cw1  = (const float*)d_in[19];
    const float* cb1  = (const float*)d_in[20];
    const float* cw2  = (const float*)d_in[21];
    const float* cb2  = (const float*)d_in[22];

    cudaFuncSetAttribute(gemm_tf32<24,0>, cudaFuncAttributeMaxDynamicSharedMemorySize, GSMEM);
    cudaFuncSetAttribute(gemm_tf32<24,2>, cudaFuncAttributeMaxDynamicSharedMemorySize, GSMEM);
    cudaFuncSetAttribute(gemm_tf32<24,3>, cudaFuncAttributeMaxDynamicSharedMemorySize, GSMEM);
    cudaFuncSetAttribute(gemm_tf32<96,0>, cudaFuncAttributeMaxDynamicSharedMemorySize, GSMEM);
    cudaFuncSetAttribute(flash_attn, cudaFuncAttributeMaxDynamicSharedMemorySize, FSMEM);

    float *x, *t, *xt, *qkt, *ct, *ft, *pool, *chd, *bqkv;
    float *wqkvt, *wot, *w1t, *w2t;
    bf16 *vhp, *vlp;
    cudaGetSymbolAddress((void**)&x,    g_x);
    cudaGetSymbolAddress((void**)&t,    g_t);
    cudaGetSymbolAddress((void**)&xt,   g_xt);
    cudaGetSymbolAddress((void**)&qkt,  g_qkt);
    cudaGetSymbolAddress((void**)&ct,   g_ct);
    cudaGetSymbolAddress((void**)&ft,   g_ft);
    cudaGetSymbolAddress((void**)&pool, g_pool);
    cudaGetSymbolAddress((void**)&chd,  g_chd);
    cudaGetSymbolAddress((void**)&bqkv, g_bqkv);
    cudaGetSymbolAddress((void**)&vhp,  g_vh);
    cudaGetSymbolAddress((void**)&vlp,  g_vl);
    cudaGetSymbolAddress((void**)&wqkvt,g_wqkvt);
    cudaGetSymbolAddress((void**)&wot,  g_wot);
    cudaGetSymbolAddress((void**)&w1t,  g_w1t);
    cudaGetSymbolAddress((void**)&w2t,  g_w2t);

    embed_kernel<<<ROWS, 256>>>(ids, emb, x, xt);
    wprep_qkv3<<<dim3(D_/32, D_/32, L_*3), 256>>>(wq, wk, wv, wqkvt);
    wprep_rest<<<dim3(5185, L_), 256>>>(wo, w1, w2, bq, bk, bv,
        wot, w1t, w2t, bqkv);

    dim3 gQKV(QKVN/128, ROWS/128);
    dim3 gDD(D_/128, ROWS/128);
    dim3 gF1(DFF_/128, ROWS/128);

    for (int l = 0; l < L_; l++) {
        gemm_tf32<24,3><<<gQKV, 256, GSMEM>>>(xt, D_,
            wqkvt + (size_t)l*QKVN*D_, D_,
            bqkv + (size_t)l*QKVN, qkt, vhp, vlp, nullptr, QKN);

        flash_attn<<<dim3(S_/128, BH_), 256, FSMEM>>>(
            qkt, vhp, vlp, relb + (size_t)l*(2*S_-1)*H_, ct);

        gemm_tf32<24,0><<<gDD, 256, GSMEM>>>(ct, D_,
            wot + (size_t)l*D_*D_, D_,
            bo + l*D_, t, nullptr, nullptr, nullptr, D_);
        add_ln<<<ROWS/8, 256>>>(x, t, l1g + l*D_, l1b + l*D_, xt);

        gemm_tf32<24,2><<<gF1, 256, GSMEM>>>(xt, D_,
            w1t + (size_t)l*D_*DFF_, D_,
            b1 + l*DFF_, nullptr, nullptr, nullptr, ft, DFF_);
        gemm_tf32<96,0><<<gDD, 256, GSMEM>>>(ft, DFF_,
            w2t + (size_t)l*DFF_*D_, DFF_,
            b2 + l*D_, t, nullptr, nullptr, nullptr, D_);
        add_ln<<<ROWS/8, 256>>>(x, t, l2g + l*D_, l2b + l*D_, xt);
    }

    meanpool<<<dim3(D_/256, B_), 256>>>(x, pool);
    fc1<<<(B_*(D_/2))/256, 256>>>(pool, cw1, cb1, chd);
    fc2<<<(B_*NC_ + 255)/256, 256>>>(chd, cw2, cb2, (float*)d_out);
}